// round 11
// baseline (speedup 1.0000x reference)
#include <cuda_runtime.h>

// Problem constants: B=64, D=2048, UNITS=1024, NW=64
#define Dd     2048
#define UNITSn 1024
#define NWn    64
#define Bsz    64

// Dense effective weight, K-blocked & unit-interleaved:
//   g_W[kb][ug][k32][u8],  kb=k>>5 (64), ug=u>>3 (128), k32=k&31, u8=u&7.
// Units adjacent in memory -> GEMM packs 2 units per f32x2. 8 MB.
__device__ float g_W[64 * 128 * 32 * 8];

__device__ __forceinline__ void fma2(unsigned long long& d,
                                     unsigned long long a,
                                     unsigned long long b) {
    asm("fma.rn.f32x2 %0, %1, %2, %0;" : "+l"(d) : "l"(a), "l"(b));
}
__device__ __forceinline__ unsigned long long pack2(float lo, float hi) {
    unsigned long long r;
    asm("mov.b64 %0, {%1, %2};" : "=l"(r) : "f"(lo), "f"(hi));
    return r;
}
__device__ __forceinline__ unsigned mdiv(unsigned e, unsigned magic) {
    return (unsigned)(((unsigned long long)e * magic) >> 32);
}

// ---------------------------------------------------------------------------
// Kernel 1: build W for one unit-group (8 units) per block, staged in smem as
// st[k][u8] with stride 9 (conflict-spread scatter), dumped coalesced into the
// blocked g_W layout. Also seeds out with bias (out is poisoned by harness).
// ---------------------------------------------------------------------------
#define STR 9
__global__ __launch_bounds__(512) void build_w_kernel(const int* __restrict__ indices,
                                                      const float* __restrict__ w,
                                                      const float* __restrict__ bias,
                                                      float* __restrict__ out,
                                                      int L, unsigned magicL) {
    __shared__ float st[Dd * STR];     // [2048 k][9] (8 units + pad) = 73.7KB
    __shared__ float wsm[NWn];
    const int tid = threadIdx.x;
    const int ug  = blockIdx.x;        // 128 blocks, one unit-group each
    const int u0  = ug * 8;

    // Seed out = bias (128 blocks x 512 = 65536 = B*UNITS).
    {
        int g = ug * 512 + tid;
        out[g] = bias[g & (UNITSn - 1)];
    }
    if (tid < NWn) wsm[tid] = w[tid];
    #pragma unroll
    for (int i = 0; i < (Dd * STR + 2047) / 2048; i++) {
        int idx = i * 2048 + tid * 4;
        if (idx + 3 < Dd * STR) *(float4*)(st + idx) = make_float4(0.f, 0.f, 0.f, 0.f);
    }
    // cover tail of the zero region
    for (int idx = (Dd * STR / 2048) * 2048 + tid; idx < Dd * STR; idx += 512)
        st[idx] = 0.f;
    __syncthreads();

    // Scatter: st[p*STR + uu] = w[bucket]. int4 loads, 16 in flight.
    {
        const int NWL4 = 16 * L;                       // int4 count per unit
        const int4* ind4 = (const int4*)indices + (long)u0 * NWL4;
        int e4 = tid;
        for (; e4 + 512 < NWL4; e4 += 1024) {
            int4 v[8], v2[8];
            #pragma unroll
            for (int uu = 0; uu < 8; uu++) {
                v[uu]  = __ldg(ind4 + (long)uu * NWL4 + e4);
                v2[uu] = __ldg(ind4 + (long)uu * NWL4 + e4 + 512);
            }
            #pragma unroll
            for (int h = 0; h < 2; h++) {
                const int4* vv = h ? v2 : v;
                const int e = (e4 + h * 512) * 4;
                const unsigned k0 = mdiv(e,     magicL);
                const unsigned k1 = mdiv(e + 1, magicL);
                const unsigned k2 = mdiv(e + 2, magicL);
                const unsigned k3 = mdiv(e + 3, magicL);
                #pragma unroll
                for (int uu = 0; uu < 8; uu++) {
                    unsigned p;
                    p = (unsigned)(vv[uu].x - 1); if (p < (unsigned)Dd) st[p * STR + uu] = wsm[k0];
                    p = (unsigned)(vv[uu].y - 1); if (p < (unsigned)Dd) st[p * STR + uu] = wsm[k1];
                    p = (unsigned)(vv[uu].z - 1); if (p < (unsigned)Dd) st[p * STR + uu] = wsm[k2];
                    p = (unsigned)(vv[uu].w - 1); if (p < (unsigned)Dd) st[p * STR + uu] = wsm[k3];
                }
            }
        }
        for (; e4 < NWL4; e4 += 512) {
            int4 v[8];
            #pragma unroll
            for (int uu = 0; uu < 8; uu++)
                v[uu] = __ldg(ind4 + (long)uu * NWL4 + e4);
            const int e = e4 * 4;
            const unsigned k0 = mdiv(e,     magicL);
            const unsigned k1 = mdiv(e + 1, magicL);
            const unsigned k2 = mdiv(e + 2, magicL);
            const unsigned k3 = mdiv(e + 3, magicL);
            #pragma unroll
            for (int uu = 0; uu < 8; uu++) {
                unsigned p;
                p = (unsigned)(v[uu].x - 1); if (p < (unsigned)Dd) st[p * STR + uu] = wsm[k0];
                p = (unsigned)(v[uu].y - 1); if (p < (unsigned)Dd) st[p * STR + uu] = wsm[k1];
                p = (unsigned)(v[uu].z - 1); if (p < (unsigned)Dd) st[p * STR + uu] = wsm[k2];
                p = (unsigned)(v[uu].w - 1); if (p < (unsigned)Dd) st[p * STR + uu] = wsm[k3];
            }
        }
    }
    __syncthreads();

    // Dump: 16384 floats, coalesced 4B stores into blocked layout.
    #pragma unroll
    for (int i = 0; i < 32; i++) {
        int o  = i * 512 + tid;          // 0..16383
        int k  = o >> 3;
        int u8 = o & 7;
        g_W[(((long)(k >> 5) * 128 + ug) * 32 + (k & 31)) * 8 + u8] = st[k * STR + u8];
    }
}

// ---------------------------------------------------------------------------
// Kernel 2: GEMM out[b, u0+j] += sum_k x[b,k] * W[u,k], grid (128 ug, 4 ksplit).
// 256 threads, <=128 regs => 2 CTAs/SM (4 warps/SMSP). Warp z owns rows z+8r;
// lane owns k = k0 + lane + 32t. W LDG.128 x2 gives 8 adjacent units at this k;
// x scalar is broadcast-packed into f32x2; acc packs unit pairs (32 ull).
// Barrier-free mainloop, 1-tile lookahead on x and W. red.add epilogue.
// ---------------------------------------------------------------------------
#define GNT  256
#define RPAD 65
__global__ __launch_bounds__(GNT, 2) void gemm_kernel(const float* __restrict__ x,
                                                      float* __restrict__ out) {
    extern __shared__ float red[];   // [256][RPAD] = 66.6KB
    const int tid  = threadIdx.x;
    const int lane = tid & 31;
    const int z    = tid >> 5;              // warp id: rows z + 8r
    const int ug   = blockIdx.x;            // unit group (8 units)
    const int u0   = ug * 8;
    const int k0   = blockIdx.y * 512;      // k-split quarter
    const int NTk  = 16;                    // 512 / 32 k per tile

    const float* xp = x + (long)z * Dd + k0 + lane;
    const float4* wp = (const float4*)g_W
                     + ((long)(blockIdx.y * 16) * 128 + ug) * 64 + lane * 2;

    // Prologue: tile 0.
    float  xa[8];
    float4 wa0, wa1;
    #pragma unroll
    for (int r = 0; r < 8; r++) xa[r] = __ldg(xp + (long)r * 8 * Dd);
    wa0 = __ldg(wp);
    wa1 = __ldg(wp + 1);

    unsigned long long acc[8][4];
    #pragma unroll
    for (int r = 0; r < 8; r++)
        #pragma unroll
        for (int jp = 0; jp < 4; jp++) acc[r][jp] = 0ULL;

    for (int t = 0; t < NTk; t++) {
        // 1-tile lookahead: next x (8 coalesced LDG.32) + next W (2 LDG.128).
        float  xn[8];
        float4 wn0, wn1;
        if (t + 1 < NTk) {
            #pragma unroll
            for (int r = 0; r < 8; r++)
                xn[r] = __ldg(xp + (long)r * 8 * Dd + (t + 1) * 32);
            const float4* wq = wp + (long)(t + 1) * 8192;   // next kb: 128*64 f4
            wn0 = __ldg(wq);
            wn1 = __ldg(wq + 1);
        }

        unsigned long long wpair[4];
        wpair[0] = pack2(wa0.x, wa0.y);   // units u0+0, u0+1
        wpair[1] = pack2(wa0.z, wa0.w);   // u0+2, u0+3
        wpair[2] = pack2(wa1.x, wa1.y);   // u0+4, u0+5
        wpair[3] = pack2(wa1.z, wa1.w);   // u0+6, u0+7

        #pragma unroll
        for (int r = 0; r < 8; r++) {
            unsigned long long xd = pack2(xa[r], xa[r]);    // broadcast x
            #pragma unroll
            for (int jp = 0; jp < 4; jp++)
                fma2(acc[r][jp], xd, wpair[jp]);
        }

        #pragma unroll
        for (int r = 0; r < 8; r++) xa[r] = xn[r];
        wa0 = wn0; wa1 = wn1;
    }

    // Epilogue: cross-lane k-reduction via padded smem, then red.add partials.
    #pragma unroll
    for (int r = 0; r < 8; r++)
        #pragma unroll
        for (int jp = 0; jp < 4; jp++) {
            unsigned long long v = acc[r][jp];
            red[(z * 32 + lane) * RPAD + r * 8 + jp * 2]     =
                __uint_as_float((unsigned)(v & 0xffffffffu));
            red[(z * 32 + lane) * RPAD + r * 8 + jp * 2 + 1] =
                __uint_as_float((unsigned)(v >> 32));
        }
    __syncthreads();

    #pragma unroll
    for (int o = tid; o < 512; o += GNT) {
        const int row  = o >> 3;            // batch row
        const int j    = o & 7;             // unit within group
        const int zz   = row & 7;           // producing warp
        const int slot = (row >> 3) * 8 + j;
        float s = 0.f;
        #pragma unroll
        for (int l = 0; l < 32; l++)
            s += red[(zz * 32 + l) * RPAD + slot];
        atomicAdd(out + (long)row * UNITSn + u0 + j, s);
    }
}

// ---------------------------------------------------------------------------
// Launch: build_w (also seeds out=bias) ; gemm   (single stream => ordered)
// ---------------------------------------------------------------------------
extern "C" void kernel_launch(void* const* d_in, const int* in_sizes, int n_in,
                              void* d_out, int out_size) {
    const float* x       = (const float*)d_in[0];
    const float* w       = (const float*)d_in[1];
    const float* bias    = (const float*)d_in[2];
    const int*   indices = (const int*)d_in[3];
    float*       out     = (float*)d_out;

    const int L = in_sizes[3] / (UNITSn * NWn);
    const unsigned magicL =
        (unsigned)((0x100000000ULL + (unsigned long long)L - 1) / (unsigned long long)L);

    const int gemm_smem = GNT * RPAD * (int)sizeof(float);   // 66,560 B
    cudaFuncSetAttribute(gemm_kernel, cudaFuncAttributeMaxDynamicSharedMemorySize,
                         gemm_smem);

    build_w_kernel<<<128, 512>>>(indices, w, bias, out, L, magicL);
    gemm_kernel<<<dim3(128, 4), GNT, gemm_smem>>>(x, out);
}

// round 13
// speedup vs baseline: 1.3333x; 1.3333x over previous
#include <cuda_runtime.h>
#include <cuda_bf16.h>
#include <cstdint>

// Problem constants: B=64, D=2048, UNITS=1024, NW=64
#define Dd     2048
#define UNITSn 1024
#define NWn    64

// W bf16 hi/lo planes, row-major [u][k] (4MB each); k-split partials [ks][b][u].
__device__ __align__(16) __nv_bfloat16 g_Whi[UNITSn * Dd];
__device__ __align__(16) __nv_bfloat16 g_Wlo[UNITSn * Dd];
__device__ float g_partial[8 * 64 * UNITSn];   // 2MB

__device__ __forceinline__ unsigned mdiv(unsigned e, unsigned magic) {
    return (unsigned)(((unsigned long long)e * magic) >> 32);
}
__device__ __forceinline__ unsigned pack_bf16x2(float f0, float f1) {
    unsigned short a = __bfloat16_as_ushort(__float2bfloat16_rn(f0));
    unsigned short b = __bfloat16_as_ushort(__float2bfloat16_rn(f1));
    return (unsigned)a | ((unsigned)b << 16);
}
__device__ __forceinline__ float bf16_hi_f(float f) {
    return __bfloat162float(__float2bfloat16_rn(f));
}
__device__ __forceinline__ unsigned smem_u32(const void* p) {
    unsigned a;
    asm("{ .reg .u64 t; cvta.to.shared.u64 t, %1; cvt.u32.u64 %0, t; }"
        : "=r"(a) : "l"(p));
    return a;
}
__device__ __forceinline__ void cp16(unsigned s, const void* g) {
    asm volatile("cp.async.cg.shared.global [%0], [%1], 16;" :: "r"(s), "l"(g));
}
__device__ __forceinline__ void cp_commit() { asm volatile("cp.async.commit_group;"); }
__device__ __forceinline__ void cp_wait_all() {
    asm volatile("cp.async.wait_group 0;" ::: "memory");
}

// HMMA m16n8k16 bf16 -> fp32 accumulate (base sm_80+ feature, sm_103-safe).
__device__ __forceinline__ void mma_bf16(float* d, unsigned a0, unsigned a1,
                                         unsigned a2, unsigned a3,
                                         unsigned b0, unsigned b1) {
    asm volatile(
        "mma.sync.aligned.m16n8k16.row.col.f32.bf16.bf16.f32 "
        "{%0,%1,%2,%3}, {%4,%5,%6,%7}, {%8,%9}, {%0,%1,%2,%3};"
        : "+f"(d[0]), "+f"(d[1]), "+f"(d[2]), "+f"(d[3])
        : "r"(a0), "r"(a1), "r"(a2), "r"(a3), "r"(b0), "r"(b1));
}

// ---------------------------------------------------------------------------
// Kernel 1: build W bf16 hi/lo planes. One block per 8 units (128 blocks).
// Scatter w[bucket] into st[k][u8] (stride 9), then split & dump row-major
// (uint2 = 4 bf16 per store, fully coalesced).
// ---------------------------------------------------------------------------
#define STR 9
__global__ __launch_bounds__(512) void build_w_kernel(const int* __restrict__ indices,
                                                      const float* __restrict__ w,
                                                      int L, unsigned magicL) {
    __shared__ float st[Dd * STR];     // 73.7 KB
    __shared__ float wsm[NWn];
    const int tid = threadIdx.x;
    const int u0  = blockIdx.x * 8;

    if (tid < NWn) wsm[tid] = w[tid];
    #pragma unroll
    for (int i = 0; i < (Dd * STR / 4) / 512; i++)
        ((float4*)st)[i * 512 + tid] = make_float4(0.f, 0.f, 0.f, 0.f);
    __syncthreads();

    {   // Scatter (int4 index loads, 16 in flight)
        const int NWL4 = 16 * L;
        const int4* ind4 = (const int4*)indices + (long)u0 * NWL4;
        int e4 = tid;
        for (; e4 + 512 < NWL4; e4 += 1024) {
            int4 v[8], v2[8];
            #pragma unroll
            for (int uu = 0; uu < 8; uu++) {
                v[uu]  = __ldg(ind4 + (long)uu * NWL4 + e4);
                v2[uu] = __ldg(ind4 + (long)uu * NWL4 + e4 + 512);
            }
            #pragma unroll
            for (int h = 0; h < 2; h++) {
                const int4* vv = h ? v2 : v;
                const int e = (e4 + h * 512) * 4;
                const unsigned k0 = mdiv(e, magicL),     k1 = mdiv(e + 1, magicL);
                const unsigned k2 = mdiv(e + 2, magicL), k3 = mdiv(e + 3, magicL);
                #pragma unroll
                for (int uu = 0; uu < 8; uu++) {
                    unsigned p;
                    p = (unsigned)(vv[uu].x - 1); if (p < (unsigned)Dd) st[p * STR + uu] = wsm[k0];
                    p = (unsigned)(vv[uu].y - 1); if (p < (unsigned)Dd) st[p * STR + uu] = wsm[k1];
                    p = (unsigned)(vv[uu].z - 1); if (p < (unsigned)Dd) st[p * STR + uu] = wsm[k2];
                    p = (unsigned)(vv[uu].w - 1); if (p < (unsigned)Dd) st[p * STR + uu] = wsm[k3];
                }
            }
        }
        for (; e4 < NWL4; e4 += 512) {
            int4 v[8];
            #pragma unroll
            for (int uu = 0; uu < 8; uu++)
                v[uu] = __ldg(ind4 + (long)uu * NWL4 + e4);
            const int e = e4 * 4;
            const unsigned k0 = mdiv(e, magicL),     k1 = mdiv(e + 1, magicL);
            const unsigned k2 = mdiv(e + 2, magicL), k3 = mdiv(e + 3, magicL);
            #pragma unroll
            for (int uu = 0; uu < 8; uu++) {
                unsigned p;
                p = (unsigned)(v[uu].x - 1); if (p < (unsigned)Dd) st[p * STR + uu] = wsm[k0];
                p = (unsigned)(v[uu].y - 1); if (p < (unsigned)Dd) st[p * STR + uu] = wsm[k1];
                p = (unsigned)(v[uu].z - 1); if (p < (unsigned)Dd) st[p * STR + uu] = wsm[k2];
                p = (unsigned)(v[uu].w - 1); if (p < (unsigned)Dd) st[p * STR + uu] = wsm[k3];
            }
        }
    }
    __syncthreads();

    // Dump: hi/lo bf16, row-major, coalesced uint2 stores (4 bf16 each).
    const int k4 = tid * 4;                       // 512 threads cover 2048 k
    #pragma unroll
    for (int uu = 0; uu < 8; uu++) {
        float f[4], hi[4];
        #pragma unroll
        for (int j = 0; j < 4; j++) {
            f[j]  = st[(k4 + j) * STR + uu];
            hi[j] = bf16_hi_f(f[j]);
        }
        uint2 hv, lv;
        hv.x = pack_bf16x2(hi[0], hi[1]);
        hv.y = pack_bf16x2(hi[2], hi[3]);
        lv.x = pack_bf16x2(f[0] - hi[0], f[1] - hi[1]);
        lv.y = pack_bf16x2(f[2] - hi[2], f[3] - hi[3]);
        const long idx = (long)(u0 + uu) * Dd + k4;
        *(uint2*)&g_Whi[idx] = hv;
        *(uint2*)&g_Wlo[idx] = lv;
    }
}

// ---------------------------------------------------------------------------
// Kernel 2: HMMA GEMM. Grid (16 ug, 8 ks), 256 threads (8 warps).
// Per CTA: units [ug*64, +64), k [ks*256, +256). W hi/lo via cp.async; x
// converted to bf16 hi/lo in smem. Warp w owns batch tile m0=(w&3)*16 and
// unit tile n0=(w>>2)*32; 3 passes (xh*Wh + xl*Wh + xh*Wl) x 16 k-steps x
// 4 n-subtiles, fp32 accumulators. Smem rows padded to 132 words ->
// all fragment LDS conflict-free. One barrier; partials to g_partial.
// ---------------------------------------------------------------------------
#define ROWW  132                      // smem row stride in 32-bit words
#define WS_HI 0
#define WS_LO (64 * ROWW)
#define XS_HI (128 * ROWW)
#define XS_LO (192 * ROWW)
#define SM_WORDS (256 * ROWW)          // 33792 words = 135168 B

__global__ __launch_bounds__(256, 1) void gemm_kernel(const float* __restrict__ x) {
    extern __shared__ unsigned smw[];
    const unsigned sbase = smem_u32(smw);
    const int tid  = threadIdx.x;
    const int lane = tid & 31;
    const int warp = tid >> 5;
    const int u0   = blockIdx.x * 64;
    const int ks   = blockIdx.y;
    const int k0   = ks * 256;

    // W: cp.async both planes (64 rows x 512B each, into padded rows).
    #pragma unroll
    for (int i = 0; i < 8; i++) {
        const int idx = i * 256 + tid;       // 0..2047 16B-chunks
        const int u   = idx >> 5;
        const int c   = idx & 31;
        const long gsrc = (long)(u0 + u) * Dd + k0 + c * 8;
        cp16(sbase + (WS_HI + u * ROWW + c * 4) * 4, &g_Whi[gsrc]);
        cp16(sbase + (WS_LO + u * ROWW + c * 4) * 4, &g_Wlo[gsrc]);
    }
    cp_commit();

    // x: load fp32, split to bf16 hi/lo, store to padded smem rows.
    #pragma unroll
    for (int it = 0; it < 8; it++) {
        const int o  = it * 256 + tid;       // 0..2047 8-elem groups
        const int b  = o >> 5;
        const int kq = o & 31;
        const float* src = x + (long)b * Dd + k0 + kq * 8;
        float4 f0 = __ldg((const float4*)src);
        float4 f1 = __ldg((const float4*)src + 1);
        float f[8] = {f0.x, f0.y, f0.z, f0.w, f1.x, f1.y, f1.z, f1.w};
        float hi[8];
        #pragma unroll
        for (int j = 0; j < 8; j++) hi[j] = bf16_hi_f(f[j]);
        uint4 hv, lv;
        hv.x = pack_bf16x2(hi[0], hi[1]); hv.y = pack_bf16x2(hi[2], hi[3]);
        hv.z = pack_bf16x2(hi[4], hi[5]); hv.w = pack_bf16x2(hi[6], hi[7]);
        lv.x = pack_bf16x2(f[0] - hi[0], f[1] - hi[1]);
        lv.y = pack_bf16x2(f[2] - hi[2], f[3] - hi[3]);
        lv.z = pack_bf16x2(f[4] - hi[4], f[5] - hi[5]);
        lv.w = pack_bf16x2(f[6] - hi[6], f[7] - hi[7]);
        *(uint4*)(smw + XS_HI + b * ROWW + kq * 4) = hv;
        *(uint4*)(smw + XS_LO + b * ROWW + kq * 4) = lv;
    }

    cp_wait_all();
    __syncthreads();

    // Fragments: g = lane>>2 (row/col group), tig = lane&3 (k sub-pair).
    const int g   = lane >> 2;
    const int tig = lane & 3;
    const int m0  = (warp & 3) * 16;
    const int n0  = (warp >> 2) * 32;

    const unsigned* ah0 = smw + XS_HI + (m0 + g) * ROWW + tig;
    const unsigned* ah8 = ah0 + 8 * ROWW;
    const unsigned* al0 = ah0 + (XS_LO - XS_HI);
    const unsigned* al8 = ah8 + (XS_LO - XS_HI);

    float d[4][4];
    #pragma unroll
    for (int j = 0; j < 4; j++)
        #pragma unroll
        for (int i = 0; i < 4; i++) d[j][i] = 0.f;

    #pragma unroll 4
    for (int s = 0; s < 16; s++) {
        const int co = s * 8;
        const unsigned xh0 = ah0[co], xh1 = ah8[co], xh2 = ah0[co + 4], xh3 = ah8[co + 4];
        const unsigned xl0 = al0[co], xl1 = al8[co], xl2 = al0[co + 4], xl3 = al8[co + 4];
        #pragma unroll
        for (int j = 0; j < 4; j++) {
            const unsigned* wb = smw + WS_HI + (n0 + j * 8 + g) * ROWW + tig;
            const unsigned bh0 = wb[co], bh1 = wb[co + 4];
            const unsigned bl0 = wb[WS_LO + co], bl1 = wb[WS_LO + co + 4];
            mma_bf16(d[j], xh0, xh1, xh2, xh3, bh0, bh1);   // hi*hi
            mma_bf16(d[j], xl0, xl1, xl2, xl3, bh0, bh1);   // lo*hi
            mma_bf16(d[j], xh0, xh1, xh2, xh3, bl0, bl1);   // hi*lo
        }
    }

    // Store partials: d0,d1 -> (b=m0+g, u=..2tig, +1); d2,d3 -> b+8.
    #pragma unroll
    for (int j = 0; j < 4; j++) {
        const int u = u0 + n0 + j * 8 + 2 * tig;
        float* p = g_partial + ((long)(ks * 64 + m0 + g) << 10) + u;
        *(float2*)p            = make_float2(d[j][0], d[j][1]);
        *(float2*)(p + (8 << 10)) = make_float2(d[j][2], d[j][3]);
    }
}

// ---------------------------------------------------------------------------
// Kernel 3: reduce 8 k-split partials + bias -> out[b][u]. 128 x 512.
// ---------------------------------------------------------------------------
__global__ __launch_bounds__(512) void reduce_kernel(const float* __restrict__ bias,
                                                     float* __restrict__ out) {
    const int o = blockIdx.x * 512 + threadIdx.x;   // 0..65535
    const int b = o >> 10;
    const int u = o & 1023;
    float s = __ldg(bias + u);
    #pragma unroll
    for (int ks = 0; ks < 8; ks++)
        s += g_partial[((long)(ks * 64 + b) << 10) + u];
    out[(long)b * UNITSn + u] = s;
}

// ---------------------------------------------------------------------------
extern "C" void kernel_launch(void* const* d_in, const int* in_sizes, int n_in,
                              void* d_out, int out_size) {
    const float* x       = (const float*)d_in[0];
    const float* w       = (const float*)d_in[1];
    const float* bias    = (const float*)d_in[2];
    const int*   indices = (const int*)d_in[3];
    float*       out     = (float*)d_out;

    const int L = in_sizes[3] / (UNITSn * NWn);
    const unsigned magicL =
        (unsigned)((0x100000000ULL + (unsigned long long)L - 1) / (unsigned long long)L);

    const int gemm_smem = SM_WORDS * (int)sizeof(unsigned);   // 135,168 B
    cudaFuncSetAttribute(gemm_kernel, cudaFuncAttributeMaxDynamicSharedMemorySize,
                         gemm_smem);

    build_w_kernel<<<128, 512>>>(indices, w, L, magicL);
    gemm_kernel<<<dim3(16, 8), 256, gemm_smem>>>(x);
    reduce_kernel<<<128, 512>>>(bias, out);
}

// round 14
// speedup vs baseline: 1.7279x; 1.2959x over previous
#include <cuda_runtime.h>
#include <cuda_bf16.h>
#include <cstdint>

// Problem constants: B=64, D=2048, UNITS=1024, NW=64
#define Dd     2048
#define UNITSn 1024
#define NWn    64

// W bf16 hi/lo planes, row-major [u][k] (4MB each).
__device__ __align__(16) __nv_bfloat16 g_Whi[UNITSn * Dd];
__device__ __align__(16) __nv_bfloat16 g_Wlo[UNITSn * Dd];

__device__ __forceinline__ unsigned mdiv(unsigned e, unsigned magic) {
    return (unsigned)(((unsigned long long)e * magic) >> 32);
}
__device__ __forceinline__ unsigned pack_bf16x2(float f0, float f1) {
    unsigned short a = __bfloat16_as_ushort(__float2bfloat16_rn(f0));
    unsigned short b = __bfloat16_as_ushort(__float2bfloat16_rn(f1));
    return (unsigned)a | ((unsigned)b << 16);
}
__device__ __forceinline__ float bf16_hi_f(float f) {
    return __bfloat162float(__float2bfloat16_rn(f));
}
__device__ __forceinline__ unsigned smem_u32(const void* p) {
    unsigned a;
    asm("{ .reg .u64 t; cvta.to.shared.u64 t, %1; cvt.u32.u64 %0, t; }"
        : "=r"(a) : "l"(p));
    return a;
}
__device__ __forceinline__ void cp16(unsigned s, const void* g) {
    asm volatile("cp.async.cg.shared.global [%0], [%1], 16;" :: "r"(s), "l"(g));
}
__device__ __forceinline__ void cp_commit() { asm volatile("cp.async.commit_group;"); }
__device__ __forceinline__ void cp_wait_all() {
    asm volatile("cp.async.wait_group 0;" ::: "memory");
}

// HMMA m16n8k16 bf16 -> fp32 accumulate (base sm_80+ feature, sm_103-safe).
__device__ __forceinline__ void mma_bf16(float* d, unsigned a0, unsigned a1,
                                         unsigned a2, unsigned a3,
                                         unsigned b0, unsigned b1) {
    asm volatile(
        "mma.sync.aligned.m16n8k16.row.col.f32.bf16.bf16.f32 "
        "{%0,%1,%2,%3}, {%4,%5,%6,%7}, {%8,%9}, {%0,%1,%2,%3};"
        : "+f"(d[0]), "+f"(d[1]), "+f"(d[2]), "+f"(d[3])
        : "r"(a0), "r"(a1), "r"(a2), "r"(a3), "r"(b0), "r"(b1));
}

// ---------------------------------------------------------------------------
// Kernel 1: build W bf16 hi/lo planes. 512 CTAs x 256 thr, 2 units per CTA
// (4x the parallelism of R13's builder; 17KB smem => high residency).
// The 64 w values are hi/lo-split ONCE into packed u32 (hi|lo<<16); the
// scatter stores a single 4B value per position into st[uu][k] (transposed
// layout => the dump is conflict-free uint4 LDS + byte_perm + coalesced
// uint2 stores per plane). Also seeds out = bias for the GEMM's atomics.
// ---------------------------------------------------------------------------
#define BTHR 256
#define KSTR 2080    // st row stride in u32
__global__ __launch_bounds__(BTHR) void build_w_kernel(const int* __restrict__ indices,
                                                       const float* __restrict__ w,
                                                       const float* __restrict__ bias,
                                                       float* __restrict__ out,
                                                       int L, unsigned magicL) {
    __shared__ unsigned st[2 * KSTR];     // [2 units][2048 k + pad] packed hi/lo
    __shared__ unsigned wpk[NWn];
    const int tid = threadIdx.x;
    const int u0  = blockIdx.x * 2;

    // Seed out = bias (512 blocks x 128 = 65536 = B*UNITS).
    if (tid < 128) {
        const int o = blockIdx.x * 128 + tid;
        out[o] = bias[o & (UNITSn - 1)];
    }
    // Precompute packed hi/lo bf16 of the 64 w values.
    if (tid < NWn) {
        const float wv = w[tid];
        const float h  = bf16_hi_f(wv);
        wpk[tid] = (unsigned)__bfloat16_as_ushort(__float2bfloat16_rn(h)) |
                   ((unsigned)__bfloat16_as_ushort(__float2bfloat16_rn(wv - h)) << 16);
    }
    // Zero st.
    #pragma unroll
    for (int i = 0; i < (2 * KSTR + 4 * BTHR - 1) / (4 * BTHR); i++) {
        const int idx = (i * BTHR + tid) * 4;
        if (idx + 3 < 2 * KSTR)
            *(uint4*)(st + idx) = make_uint4(0u, 0u, 0u, 0u);
    }
    for (int idx = (2 * KSTR / (4 * BTHR)) * 4 * BTHR + tid; idx < 2 * KSTR; idx += BTHR)
        st[idx] = 0u;
    __syncthreads();

    // Scatter: st[uu*KSTR + p] = wpk[bucket]. int4 index loads, 2-deep (4 in flight).
    {
        const int NWL4 = 16 * L;
        const int4* ind4 = (const int4*)indices + (long)u0 * NWL4;
        int e4 = tid;
        for (; e4 + BTHR < NWL4; e4 += 2 * BTHR) {
            int4 v[2], v2[2];
            #pragma unroll
            for (int uu = 0; uu < 2; uu++) {
                v[uu]  = __ldg(ind4 + (long)uu * NWL4 + e4);
                v2[uu] = __ldg(ind4 + (long)uu * NWL4 + e4 + BTHR);
            }
            #pragma unroll
            for (int h = 0; h < 2; h++) {
                const int4* vv = h ? v2 : v;
                const int e = (e4 + h * BTHR) * 4;
                const unsigned k0 = mdiv(e, magicL),     k1 = mdiv(e + 1, magicL);
                const unsigned k2 = mdiv(e + 2, magicL), k3 = mdiv(e + 3, magicL);
                #pragma unroll
                for (int uu = 0; uu < 2; uu++) {
                    unsigned* row = st + uu * KSTR;
                    unsigned p;
                    p = (unsigned)(vv[uu].x - 1); if (p < (unsigned)Dd) row[p] = wpk[k0];
                    p = (unsigned)(vv[uu].y - 1); if (p < (unsigned)Dd) row[p] = wpk[k1];
                    p = (unsigned)(vv[uu].z - 1); if (p < (unsigned)Dd) row[p] = wpk[k2];
                    p = (unsigned)(vv[uu].w - 1); if (p < (unsigned)Dd) row[p] = wpk[k3];
                }
            }
        }
        for (; e4 < NWL4; e4 += BTHR) {
            int4 v[2];
            #pragma unroll
            for (int uu = 0; uu < 2; uu++)
                v[uu] = __ldg(ind4 + (long)uu * NWL4 + e4);
            const int e = e4 * 4;
            const unsigned k0 = mdiv(e, magicL),     k1 = mdiv(e + 1, magicL);
            const unsigned k2 = mdiv(e + 2, magicL), k3 = mdiv(e + 3, magicL);
            #pragma unroll
            for (int uu = 0; uu < 2; uu++) {
                unsigned* row = st + uu * KSTR;
                unsigned p;
                p = (unsigned)(v[uu].x - 1); if (p < (unsigned)Dd) row[p] = wpk[k0];
                p = (unsigned)(v[uu].y - 1); if (p < (unsigned)Dd) row[p] = wpk[k1];
                p = (unsigned)(v[uu].z - 1); if (p < (unsigned)Dd) row[p] = wpk[k2];
                p = (unsigned)(v[uu].w - 1); if (p < (unsigned)Dd) row[p] = wpk[k3];
            }
        }
    }
    __syncthreads();

    // Dump: uint4 = 4 packed k -> uint2 per plane via byte_perm; coalesced.
    #pragma unroll
    for (int uu = 0; uu < 2; uu++) {
        #pragma unroll
        for (int i = 0; i < 2; i++) {
            const int idx = i * BTHR + tid;             // 0..511 uint4 groups
            uint4 pk = *(const uint4*)(st + uu * KSTR + idx * 4);
            uint2 hv, lv;
            hv.x = __byte_perm(pk.x, pk.y, 0x5410);     // low halves (hi bits)
            hv.y = __byte_perm(pk.z, pk.w, 0x5410);
            lv.x = __byte_perm(pk.x, pk.y, 0x7632);     // high halves (lo bits)
            lv.y = __byte_perm(pk.z, pk.w, 0x7632);
            const long gi = (long)(u0 + uu) * Dd + idx * 4;
            *(uint2*)&g_Whi[gi] = hv;
            *(uint2*)&g_Wlo[gi] = lv;
        }
    }
}

// ---------------------------------------------------------------------------
// Kernel 2: HMMA GEMM. Grid (16 ug, 8 ks), 256 threads (8 warps).
// Per CTA: units [ug*64, +64), k [ks*256, +256). W hi/lo via cp.async; x
// converted to bf16 hi/lo in smem. Warp w owns batch tile m0=(w&3)*16 and
// unit tile n0=(w>>2)*32; 3 error-compensated passes (xh*Wh + xl*Wh + xh*Wl)
// x 16 k-steps x 4 n-subtiles, fp32 accumulators. Padded smem rows (132
// words) keep fragment LDS conflict-free. Epilogue: atomicAdd partials
// straight into the bias-seeded out (reduce kernel eliminated).
// ---------------------------------------------------------------------------
#define ROWW  132
#define WS_HI 0
#define WS_LO (64 * ROWW)
#define XS_HI (128 * ROWW)
#define XS_LO (192 * ROWW)
#define SM_WORDS (256 * ROWW)          // 135168 B

__global__ __launch_bounds__(256, 1) void gemm_kernel(const float* __restrict__ x,
                                                      float* __restrict__ out) {
    extern __shared__ unsigned smw[];
    const unsigned sbase = smem_u32(smw);
    const int tid  = threadIdx.x;
    const int lane = tid & 31;
    const int warp = tid >> 5;
    const int u0   = blockIdx.x * 64;
    const int k0   = blockIdx.y * 256;

    // W: cp.async both planes (64 rows x 512B each, into padded rows).
    #pragma unroll
    for (int i = 0; i < 8; i++) {
        const int idx = i * 256 + tid;       // 0..2047 16B-chunks
        const int u   = idx >> 5;
        const int c   = idx & 31;
        const long gsrc = (long)(u0 + u) * Dd + k0 + c * 8;
        cp16(sbase + (WS_HI + u * ROWW + c * 4) * 4, &g_Whi[gsrc]);
        cp16(sbase + (WS_LO + u * ROWW + c * 4) * 4, &g_Wlo[gsrc]);
    }
    cp_commit();

    // x: load fp32, split to bf16 hi/lo, store to padded smem rows.
    #pragma unroll
    for (int it = 0; it < 8; it++) {
        const int o  = it * 256 + tid;       // 0..2047 8-elem groups
        const int b  = o >> 5;
        const int kq = o & 31;
        const float* src = x + (long)b * Dd + k0 + kq * 8;
        float4 f0 = __ldg((const float4*)src);
        float4 f1 = __ldg((const float4*)src + 1);
        float f[8] = {f0.x, f0.y, f0.z, f0.w, f1.x, f1.y, f1.z, f1.w};
        float hi[8];
        #pragma unroll
        for (int j = 0; j < 8; j++) hi[j] = bf16_hi_f(f[j]);
        uint4 hv, lv;
        hv.x = pack_bf16x2(hi[0], hi[1]); hv.y = pack_bf16x2(hi[2], hi[3]);
        hv.z = pack_bf16x2(hi[4], hi[5]); hv.w = pack_bf16x2(hi[6], hi[7]);
        lv.x = pack_bf16x2(f[0] - hi[0], f[1] - hi[1]);
        lv.y = pack_bf16x2(f[2] - hi[2], f[3] - hi[3]);
        lv.z = pack_bf16x2(f[4] - hi[4], f[5] - hi[5]);
        lv.w = pack_bf16x2(f[6] - hi[6], f[7] - hi[7]);
        *(uint4*)(smw + XS_HI + b * ROWW + kq * 4) = hv;
        *(uint4*)(smw + XS_LO + b * ROWW + kq * 4) = lv;
    }

    cp_wait_all();
    __syncthreads();

    // Fragments: g = lane>>2 (row/col group), tig = lane&3 (k sub-pair).
    const int g   = lane >> 2;
    const int tig = lane & 3;
    const int m0  = (warp & 3) * 16;
    const int n0  = (warp >> 2) * 32;

    const unsigned* ah0 = smw + XS_HI + (m0 + g) * ROWW + tig;
    const unsigned* ah8 = ah0 + 8 * ROWW;
    const unsigned* al0 = ah0 + (XS_LO - XS_HI);
    const unsigned* al8 = ah8 + (XS_LO - XS_HI);

    float d[4][4];
    #pragma unroll
    for (int j = 0; j < 4; j++)
        #pragma unroll
        for (int i = 0; i < 4; i++) d[j][i] = 0.f;

    #pragma unroll 4
    for (int s = 0; s < 16; s++) {
        const int co = s * 8;
        const unsigned xh0 = ah0[co], xh1 = ah8[co], xh2 = ah0[co + 4], xh3 = ah8[co + 4];
        const unsigned xl0 = al0[co], xl1 = al8[co], xl2 = al0[co + 4], xl3 = al8[co + 4];
        #pragma unroll
        for (int j = 0; j < 4; j++) {
            const unsigned* wb = smw + WS_HI + (n0 + j * 8 + g) * ROWW + tig;
            const unsigned bh0 = wb[co], bh1 = wb[co + 4];
            const unsigned bl0 = wb[WS_LO + co], bl1 = wb[WS_LO + co + 4];
            mma_bf16(d[j], xh0, xh1, xh2, xh3, bh0, bh1);   // hi*hi
            mma_bf16(d[j], xl0, xl1, xl2, xl3, bh0, bh1);   // lo*hi
            mma_bf16(d[j], xh0, xh1, xh2, xh3, bl0, bl1);   // hi*lo
        }
    }

    // Epilogue: atomic k-split reduction into bias-seeded out.
    #pragma unroll
    for (int j = 0; j < 4; j++) {
        const int u = u0 + n0 + j * 8 + 2 * tig;
        float* p0 = out + (long)(m0 + g) * UNITSn + u;
        float* p1 = out + (long)(m0 + g + 8) * UNITSn + u;
        atomicAdd(p0,     d[j][0]);
        atomicAdd(p0 + 1, d[j][1]);
        atomicAdd(p1,     d[j][2]);
        atomicAdd(p1 + 1, d[j][3]);
    }
}

// ---------------------------------------------------------------------------
extern "C" void kernel_launch(void* const* d_in, const int* in_sizes, int n_in,
                              void* d_out, int out_size) {
    const float* x       = (const float*)d_in[0];
    const float* w       = (const float*)d_in[1];
    const float* bias    = (const float*)d_in[2];
    const int*   indices = (const int*)d_in[3];
    float*       out     = (float*)d_out;

    const int L = in_sizes[3] / (UNITSn * NWn);
    const unsigned magicL =
        (unsigned)((0x100000000ULL + (unsigned long long)L - 1) / (unsigned long long)L);

    const int gemm_smem = SM_WORDS * (int)sizeof(unsigned);   // 135,168 B
    cudaFuncSetAttribute(gemm_kernel, cudaFuncAttributeMaxDynamicSharedMemorySize,
                         gemm_smem);

    build_w_kernel<<<512, BTHR>>>(indices, w, bias, out, L, magicL);
    gemm_kernel<<<dim3(16, 8), 256, gemm_smem>>>(x, out);
}